// round 16
// baseline (speedup 1.0000x reference)
#include <cuda_runtime.h>
#include <cstdint>

// Spatial correlation via tf32 mma.sync banded GEMM (sm_80+ path, no tcgen05).
// out[b, dh*9+dw, h, w] = (1/C) sum_c in1[b,c,h,w] * in2[b,c,h+dh-4,w+dw-4]
// B=8, C=256, H=128, W=256, patch=9.
//
// CTA: 8h x 16w pixel tile, 256 threads, warp = pixel row hh.
// Warp hh: D[m=16 px][n=216 window px] as 27 (dh,t) m16n8k8 tiles x 32 k8.
// A smem [kc][m] pitch 136, B smem [kc][n] pitch 392 (both == 8 mod 32:
// fragment LDS.32 conflict-free, loader STS consecutive). 2-stage ring.

#define BB    8
#define CC_   256
#define HHH   128
#define WWW   256
#define PATCH 9

#define KC    32                 // channels per chunk
#define NCHUNK (CC_ / KC)        // 8
#define PA    136                // A pitch (words), 128 used
#define PB    392                // B pitch (words), 384 used
#define A_W   (KC * PA)          // 4352 words
#define B_W   (KC * PB)          // 12544 words
#define STG_W (A_W + B_W)        // 16896 words per stage
#define SMEM_TOTAL (2 * STG_W * 4)   // 135168 bytes
#define PE    242                // epilogue pitch (words)
#define NT    256

__device__ __forceinline__ uint32_t f2tf32(float v) {
    uint32_t r;
    asm("cvt.rna.tf32.f32 %0, %1;" : "=r"(r) : "f"(v));
    return r;
}

__device__ __forceinline__ void mma_tf32(float d[4],
                                         uint32_t a0, uint32_t a1, uint32_t a2, uint32_t a3,
                                         uint32_t b0, uint32_t b1) {
    asm("mma.sync.aligned.m16n8k8.row.col.f32.tf32.tf32.f32 "
        "{%0,%1,%2,%3}, {%4,%5,%6,%7}, {%8,%9}, {%0,%1,%2,%3};"
        : "+f"(d[0]), "+f"(d[1]), "+f"(d[2]), "+f"(d[3])
        : "r"(a0), "r"(a1), "r"(a2), "r"(a3), "r"(b0), "r"(b1));
}

__global__ void __launch_bounds__(NT, 1)
corr_kernel(const float* __restrict__ in1,
            const float* __restrict__ in2,
            float* __restrict__ out)
{
    extern __shared__ __align__(16) float smf[];

    const int tid  = threadIdx.x;
    const int lane = tid & 31;
    const int hh   = tid >> 5;        // warp id = pixel row 0..7
    const int lq   = lane >> 2;       // 0..7
    const int lr   = lane & 3;        // 0..3

    const int w0 = blockIdx.x * 16;
    const int h0 = blockIdx.y * 8;
    const int b  = blockIdx.z;
    const size_t HW = (size_t)HHH * WWW;

    const float* __restrict__ in1b = in1 + (size_t)b * CC_ * HW;
    const float* __restrict__ in2b = in2 + (size_t)b * CC_ * HW;

    // ---- loader: LDG + cvt.rna.tf32 + STS (transpose NCHW -> k-major) ----
    auto load_chunk = [&](int k) {
        float* sa = smf + (k & 1) * STG_W;
        float* sb = sa + A_W;
        const float* i1 = in1b + (size_t)k * KC * HW;
        const float* i2 = in2b + (size_t)k * KC * HW;
        // A: 32 kc x 128 px = 4096 words, 16 slots/thread
#pragma unroll
        for (int t = 0; t < 16; t++) {
            int i  = tid + t * NT;
            int kc = i >> 7;
            int p  = i & 127;
            float v = i1[(size_t)kc * HW + (size_t)(h0 + (p >> 4)) * WWW + (w0 + (p & 15))];
            ((uint32_t*)sa)[kc * PA + p] = f2tf32(v);
        }
        // B: 32 kc x 384 window px = 12288 words, 48 slots/thread
#pragma unroll
        for (int t = 0; t < 48; t++) {
            int i  = tid + t * NT;
            int kc = i / 384;
            int n  = i - kc * 384;
            int r2 = (n * 2731) >> 16;     // n / 24 for n < 384
            int cw = n - r2 * 24;
            int gh = h0 - 4 + r2;
            int gw = w0 - 4 + cw;
            bool ok = (gh >= 0) && (gh < HHH) && (gw >= 0) && (gw < WWW);
            float v = ok ? i2[(size_t)kc * HW + (size_t)gh * WWW + gw] : 0.0f;
            ((uint32_t*)sb)[kc * PB + n] = f2tf32(v);
        }
    };

    // ---- accumulators: 9 dh x 3 t x 4 ----
    float acc[PATCH][3][4];
#pragma unroll
    for (int dh = 0; dh < PATCH; dh++)
#pragma unroll
        for (int t = 0; t < 3; t++)
#pragma unroll
            for (int j = 0; j < 4; j++) acc[dh][t][j] = 0.0f;

    // one k8 step of one stage
    auto kstep = [&](const uint32_t* sa, const uint32_t* sb, int s4) {
        const int kb = s4 * 8;
        const int am = hh * 16 + lq;
        uint32_t a0 = sa[(kb + lr) * PA + am];
        uint32_t a1 = sa[(kb + lr) * PA + am + 8];
        uint32_t a2 = sa[(kb + lr + 4) * PA + am];
        uint32_t a3 = sa[(kb + lr + 4) * PA + am + 8];
#pragma unroll
        for (int dh = 0; dh < PATCH; dh++) {
#pragma unroll
            for (int t = 0; t < 3; t++) {
                const int n0 = (hh + dh) * 24 + t * 8 + lq;
                uint32_t b0 = sb[(kb + lr) * PB + n0];
                uint32_t b1 = sb[(kb + lr + 4) * PB + n0];
                mma_tf32(acc[dh][t], a0, a1, a2, a3, b0, b1);
            }
        }
    };

    // ---- main loop: 8 chunks, 2-stage ring, loader interleaved ----
    load_chunk(0);
    for (int k = 0; k < NCHUNK; k++) {
        __syncthreads();                         // stage k published; other stage free
        const uint32_t* sa = (const uint32_t*)(smf + (k & 1) * STG_W);
        const uint32_t* sb = sa + A_W;
        kstep(sa, sb, 0);
        if (k + 1 < NCHUNK) load_chunk(k + 1);   // overlap LDG latency with MMA
        kstep(sa, sb, 1);
        kstep(sa, sb, 2);
        kstep(sa, sb, 3);
    }

    // ---- epilogue: fragments -> smem (per-warp region) -> coalesced STG ----
    __syncthreads();                             // all compute done; reuse smem
    float* ep = smf + hh * (16 * PE);
#pragma unroll
    for (int dh = 0; dh < PATCH; dh++) {
#pragma unroll
        for (int t = 0; t < 3; t++) {
            const int nl = dh * 24 + t * 8 + 2 * lr;
            *(float2*)&ep[lq * PE + nl]       = make_float2(acc[dh][t][0], acc[dh][t][1]);
            *(float2*)&ep[(lq + 8) * PE + nl] = make_float2(acc[dh][t][2], acc[dh][t][3]);
        }
    }
    __syncwarp();                                // warp reads only its own region

    const float scale = 1.0f / (float)CC_;
    float* outb = out + (size_t)b * (PATCH * PATCH) * HW + (size_t)(h0 + hh) * WWW + w0;
    const int ww = lane & 15;
    for (int e2 = 0; e2 < 82; e2 += 2) {
        int e = e2 + (lane >> 4);
        if (e < 81) {
            int dh = e / PATCH;
            int dw = e - dh * PATCH;
            float v = ep[ww * PE + dh * 24 + ww + dw] * scale;
            outb[(size_t)e * HW + ww] = v;
        }
    }
}

extern "C" void kernel_launch(void* const* d_in, const int* in_sizes, int n_in,
                              void* d_out, int out_size)
{
    const float* in1 = (const float*)d_in[0];
    const float* in2 = (const float*)d_in[1];
    float* out = (float*)d_out;

    cudaFuncSetAttribute(corr_kernel,
                         cudaFuncAttributeMaxDynamicSharedMemorySize, SMEM_TOTAL);

    dim3 grid(WWW / 16, HHH / 8, BB);   // 16 x 16 x 8 = 2048 blocks
    dim3 block(NT);
    corr_kernel<<<grid, block, SMEM_TOTAL>>>(in1, in2, out);
}

// round 17
// speedup vs baseline: 1.0007x; 1.0007x over previous
#include <cuda_runtime.h>
#include <cstdint>

// Spatial correlation via tf32 mma.sync banded GEMM (sm_80+ path, no tcgen05).
// out[b, dh*9+dw, h, w] = (1/C) sum_c in1[b,c,h,w] * in2[b,c,h+dh-4,w+dw-4]
// B=8, C=256, H=128, W=256, patch=9.
//
// CTA: 8h x 16w pixel tile, 256 threads, warp = pixel row hh.
// Warp hh: D[m=16 px][n=216 window px] as 27 (dh,t) m16n8k8 tiles x 32 k8.
// A smem [kc][m] pitch 136, B smem [kc][n] pitch 392 (both == 8 mod 32:
// fragment LDS.32 conflict-free, loader STS consecutive). 2-stage ring.

#define BB    8
#define CC_   256
#define HHH   128
#define WWW   256
#define PATCH 9

#define KC    32                 // channels per chunk
#define NCHUNK (CC_ / KC)        // 8
#define PA    136                // A pitch (words), 128 used
#define PB    392                // B pitch (words), 384 used
#define A_W   (KC * PA)          // 4352 words
#define B_W   (KC * PB)          // 12544 words
#define STG_W (A_W + B_W)        // 16896 words per stage
#define SMEM_TOTAL (2 * STG_W * 4)   // 135168 bytes
#define PE    242                // epilogue pitch (words)
#define NT    256

__device__ __forceinline__ uint32_t f2tf32(float v) {
    uint32_t r;
    asm("cvt.rna.tf32.f32 %0, %1;" : "=r"(r) : "f"(v));
    return r;
}

__device__ __forceinline__ void mma_tf32(float d[4],
                                         uint32_t a0, uint32_t a1, uint32_t a2, uint32_t a3,
                                         uint32_t b0, uint32_t b1) {
    asm("mma.sync.aligned.m16n8k8.row.col.f32.tf32.tf32.f32 "
        "{%0,%1,%2,%3}, {%4,%5,%6,%7}, {%8,%9}, {%0,%1,%2,%3};"
        : "+f"(d[0]), "+f"(d[1]), "+f"(d[2]), "+f"(d[3])
        : "r"(a0), "r"(a1), "r"(a2), "r"(a3), "r"(b0), "r"(b1));
}

__global__ void __launch_bounds__(NT, 1)
corr_kernel(const float* __restrict__ in1,
            const float* __restrict__ in2,
            float* __restrict__ out)
{
    extern __shared__ __align__(16) float smf[];

    const int tid  = threadIdx.x;
    const int lane = tid & 31;
    const int hh   = tid >> 5;        // warp id = pixel row 0..7
    const int lq   = lane >> 2;       // 0..7
    const int lr   = lane & 3;        // 0..3

    const int w0 = blockIdx.x * 16;
    const int h0 = blockIdx.y * 8;
    const int b  = blockIdx.z;
    const size_t HW = (size_t)HHH * WWW;

    const float* __restrict__ in1b = in1 + (size_t)b * CC_ * HW;
    const float* __restrict__ in2b = in2 + (size_t)b * CC_ * HW;

    // ---- loader: LDG + cvt.rna.tf32 + STS (transpose NCHW -> k-major) ----
    auto load_chunk = [&](int k) {
        float* sa = smf + (k & 1) * STG_W;
        float* sb = sa + A_W;
        const float* i1 = in1b + (size_t)k * KC * HW;
        const float* i2 = in2b + (size_t)k * KC * HW;
        // A: 32 kc x 128 px = 4096 words, 16 slots/thread
#pragma unroll
        for (int t = 0; t < 16; t++) {
            int i  = tid + t * NT;
            int kc = i >> 7;
            int p  = i & 127;
            float v = i1[(size_t)kc * HW + (size_t)(h0 + (p >> 4)) * WWW + (w0 + (p & 15))];
            ((uint32_t*)sa)[kc * PA + p] = f2tf32(v);
        }
        // B: 32 kc x 384 window px = 12288 words, 48 slots/thread
#pragma unroll
        for (int t = 0; t < 48; t++) {
            int i  = tid + t * NT;
            int kc = i / 384;
            int n  = i - kc * 384;
            int r2 = (n * 2731) >> 16;     // n / 24 for n < 384
            int cw = n - r2 * 24;
            int gh = h0 - 4 + r2;
            int gw = w0 - 4 + cw;
            bool ok = (gh >= 0) && (gh < HHH) && (gw >= 0) && (gw < WWW);
            float v = ok ? i2[(size_t)kc * HW + (size_t)gh * WWW + gw] : 0.0f;
            ((uint32_t*)sb)[kc * PB + n] = f2tf32(v);
        }
    };

    // ---- accumulators: 9 dh x 3 t x 4 ----
    float acc[PATCH][3][4];
#pragma unroll
    for (int dh = 0; dh < PATCH; dh++)
#pragma unroll
        for (int t = 0; t < 3; t++)
#pragma unroll
            for (int j = 0; j < 4; j++) acc[dh][t][j] = 0.0f;

    // one k8 step of one stage
    auto kstep = [&](const uint32_t* sa, const uint32_t* sb, int s4) {
        const int kb = s4 * 8;
        const int am = hh * 16 + lq;
        uint32_t a0 = sa[(kb + lr) * PA + am];
        uint32_t a1 = sa[(kb + lr) * PA + am + 8];
        uint32_t a2 = sa[(kb + lr + 4) * PA + am];
        uint32_t a3 = sa[(kb + lr + 4) * PA + am + 8];
#pragma unroll
        for (int dh = 0; dh < PATCH; dh++) {
#pragma unroll
            for (int t = 0; t < 3; t++) {
                const int n0 = (hh + dh) * 24 + t * 8 + lq;
                uint32_t b0 = sb[(kb + lr) * PB + n0];
                uint32_t b1 = sb[(kb + lr + 4) * PB + n0];
                mma_tf32(acc[dh][t], a0, a1, a2, a3, b0, b1);
            }
        }
    };

    // ---- main loop: 8 chunks, 2-stage ring, loader interleaved ----
    load_chunk(0);
    for (int k = 0; k < NCHUNK; k++) {
        __syncthreads();                         // stage k published; other stage free
        const uint32_t* sa = (const uint32_t*)(smf + (k & 1) * STG_W);
        const uint32_t* sb = sa + A_W;
        kstep(sa, sb, 0);
        if (k + 1 < NCHUNK) load_chunk(k + 1);   // overlap LDG latency with MMA
        kstep(sa, sb, 1);
        kstep(sa, sb, 2);
        kstep(sa, sb, 3);
    }

    // ---- epilogue: fragments -> smem (per-warp region) -> coalesced STG ----
    __syncthreads();                             // all compute done; reuse smem
    float* ep = smf + hh * (16 * PE);
#pragma unroll
    for (int dh = 0; dh < PATCH; dh++) {
#pragma unroll
        for (int t = 0; t < 3; t++) {
            const int nl = dh * 24 + t * 8 + 2 * lr;
            *(float2*)&ep[lq * PE + nl]       = make_float2(acc[dh][t][0], acc[dh][t][1]);
            *(float2*)&ep[(lq + 8) * PE + nl] = make_float2(acc[dh][t][2], acc[dh][t][3]);
        }
    }
    __syncwarp();                                // warp reads only its own region

    const float scale = 1.0f / (float)CC_;
    float* outb = out + (size_t)b * (PATCH * PATCH) * HW + (size_t)(h0 + hh) * WWW + w0;
    const int ww = lane & 15;
    for (int e2 = 0; e2 < 82; e2 += 2) {
        int e = e2 + (lane >> 4);
        if (e < 81) {
            int dh = e / PATCH;
            int dw = e - dh * PATCH;
            float v = ep[ww * PE + dh * 24 + ww + dw] * scale;
            outb[(size_t)e * HW + ww] = v;
        }
    }
}

extern "C" void kernel_launch(void* const* d_in, const int* in_sizes, int n_in,
                              void* d_out, int out_size)
{
    const float* in1 = (const float*)d_in[0];
    const float* in2 = (const float*)d_in[1];
    float* out = (float*)d_out;

    cudaFuncSetAttribute(corr_kernel,
                         cudaFuncAttributeMaxDynamicSharedMemorySize, SMEM_TOTAL);

    dim3 grid(WWW / 16, HHH / 8, BB);   // 16 x 16 x 8 = 2048 blocks
    dim3 block(NT);
    corr_kernel<<<grid, block, SMEM_TOTAL>>>(in1, in2, out);
}